// round 8
// baseline (speedup 1.0000x reference)
#include <cuda_runtime.h>
#include <cstdint>

// Paillier 2x2 "sum" pooling = windowed modular product of ciphertexts mod n^2.
// n = 46337, NSQ = n^2 = 2147117569 < 2^31.
// Dtypes (established empirically R1/R4/R6/R7):
//   input  = int32  (512 MiB buffer; values < 2^31 stored losslessly)
//   output = float32 (128 MiB; raw-bit writes in R4 produced NaN casts)
//
// Montgomery multiplication with R = 2^32, lazy residues in [0, 2N):
//   mm(mm(mm(mm(a,b),c),d), R^4 mod N) == a*b*c*d mod N  (one final fixup)
// 3 IMAD-class instructions per montmul -> 12 fma-pipe ops per output.

static constexpr uint32_t NSQ = 2147117569u;  // 46337^2

// -NSQ^{-1} mod 2^32 (Newton iteration, constexpr).
static constexpr uint32_t compute_np() {
    uint32_t inv = NSQ;                       // correct mod 2^3 for odd N
    for (int i = 0; i < 5; ++i) inv *= (2u - NSQ * inv);
    return (uint32_t)(0u - inv);
}
static constexpr uint32_t NPRIME = compute_np();

// R^4 mod NSQ = 2^128 mod NSQ (repeated doubling, constexpr).
static constexpr uint32_t compute_r4() {
    uint64_t r = 1;
    for (int i = 0; i < 128; ++i) r = (r * 2u) % (uint64_t)NSQ;
    return (uint32_t)r;
}
static constexpr uint32_t R4 = compute_r4();

// a*b*R^{-1} "mod" N, result < 2N. Valid while t = a*b < N*R, which holds
// for a < 2N (< 2^32) and b < N (< 2^31).
__device__ __forceinline__ uint32_t montmul(uint32_t a, uint32_t b) {
    uint64_t t = (uint64_t)a * (uint64_t)b;         // IMAD.WIDE
    uint32_t m = (uint32_t)t * NPRIME;              // IMAD (lo32)
    uint64_t u = t + (uint64_t)m * (uint64_t)NSQ;   // IMAD.WIDE (64-bit acc)
    return (uint32_t)(u >> 32);
}

// Exact a*b*c*d mod NSQ, returned as float32 (value < 2^31, rel err ~6e-8).
__device__ __forceinline__ float pool4(uint32_t a, uint32_t b,
                                       uint32_t c, uint32_t d) {
    uint32_t x = montmul(a, b);   // a*b*R^-1          < 2N   (a<N, b<N)
    x = montmul(x, c);            // abc*R^-2          < 2N   (x<2N, c<N)
    x = montmul(x, d);            // abcd*R^-3         < 2N
    x = montmul(x, R4);           // abcd              < 2N   (R4 < N)
    uint32_t y = x - NSQ;         // branchless final reduction:
    x = min(x, y);                // unsigned min selects the in-range value
    return (float)x;              // I2F; output buffer is float32
}

// Shapes: B=32, H=256, W=256, C=64 -> Ho=Wo=128. int32 in, float32 out.
// Each thread produces 4 adjacent channels (uint4 in, float4 out).
// Threads = 32*128*128*16 = 8,388,608.
__global__ __launch_bounds__(256, 8)
void paillier_pool_kernel(const uint4* __restrict__ in,
                          float4* __restrict__ out) {
    uint32_t tid = blockIdx.x * 256u + threadIdx.x;

    uint32_t c4  = tid & 15u;          // channel group  [0,16)
    uint32_t wo  = (tid >> 4) & 127u;  // output col     [0,128)
    uint32_t hob = tid >> 11;          // b*128 + ho     [0,4096)

    // Input elem idx (b, 2ho, 2wo, 4c4) = hob*32768 + wo*128 + 4c4.
    // In uint4 units (/4): base = hob*8192 + wo*32 + c4.
    // Row stride (h+1) = W*C = 16384 elem = 4096 uint4.
    uint32_t base = hob * 8192u + wo * 32u + c4;

    uint4 v00 = in[base];            // (h=2ho,   w=2wo)
    uint4 v01 = in[base + 16u];      // (h=2ho,   w=2wo+1)   +64 elem
    uint4 v10 = in[base + 4096u];    // (h=2ho+1, w=2wo)
    uint4 v11 = in[base + 4112u];    // (h=2ho+1, w=2wo+1)

    float4 r;
    r.x = pool4(v00.x, v01.x, v10.x, v11.x);
    r.y = pool4(v00.y, v01.y, v10.y, v11.y);
    r.z = pool4(v00.z, v01.z, v10.z, v11.z);
    r.w = pool4(v00.w, v01.w, v10.w, v11.w);

    // Output elem idx (b, ho, wo, 4c4) = hob*8192 + wo*64 + 4c4.
    // In float4 units (/4): hob*2048 + wo*16 + c4.   (FIXED: was *1024 in R6)
    out[hob * 2048u + wo * 16u + c4] = r;
}

extern "C" void kernel_launch(void* const* d_in, const int* in_sizes, int n_in,
                              void* d_out, int out_size) {
    (void)in_sizes; (void)n_in; (void)out_size;
    const uint4* in = (const uint4*)d_in[0];
    float4* out = (float4*)d_out;
    // 8,388,608 threads / 256 = 32768 blocks
    paillier_pool_kernel<<<32768, 256>>>(in, out);
}